// round 9
// baseline (speedup 1.0000x reference)
#include <cuda_runtime.h>
#include <stdint.h>

// Dataset-fixed shapes. Harness delivers uint8 arrays EXPANDED to one value
// 0..255 per 32-bit element (int32 or float32 — uniform-detected at runtime).
//   weights: 524288 elems, flip: 16777216 elems (32 layers x 524288)
//   out: 524289 f32 = new_weights byte values ++ update_ratio  [or 524288 i32]
#define WORDS       131072            // packed uint32 words
#define LAYERS      32
#define TOTAL_BITS  4194304
#define LAYER_U4    131072            // uint4 per layer
#define FLIP_ELEMS  16777216
#define W_ELEMS     524288
#define NBLK        1024              // 2 threads/word: 1024*256 = 262144 thr
#define NTHR        256
#define NSTAGE      8                 // 8 stages x 2 layers = 16 layers/thread

// Monotonic counters (graph-replay-safe: each run adds exactly NBLK; target is
// the next multiple of NBLK). Zero-initialized at module load.
__device__ unsigned int g_arrive = 0;
__device__ unsigned int g_done   = 0;
__device__ unsigned int g_cnt_part[NBLK];
__device__ unsigned int g_mask_part[NBLK];

// ---- cp.async helpers (16B, L1-bypass streaming) ----
__device__ __forceinline__ void cpa16(void* sptr, const void* gptr) {
    uint32_t sa = (uint32_t)__cvta_generic_to_shared(sptr);
    asm volatile("cp.async.cg.shared.global [%0], [%1], 16;" :: "r"(sa), "l"(gptr) : "memory");
}
#define CPA_COMMIT() asm volatile("cp.async.commit_group;" ::: "memory")
#define CPA_WAIT(n)  asm volatile("cp.async.wait_group %0;" :: "n"(n) : "memory")

// 4 expanded elements -> one packed byte word (elem k -> byte k)
__device__ __forceinline__ uint32_t pack4i(uint4 v) {   // int32-expanded path
    return __byte_perm(__byte_perm(v.x, v.y, 0x0040),
                       __byte_perm(v.z, v.w, 0x0040), 0x5410);
}
__device__ __forceinline__ uint32_t pack4f(uint4 v) {   // float32-expanded path
    uint32_t b0 = (uint32_t)__uint_as_float(v.x), b1 = (uint32_t)__uint_as_float(v.y);
    uint32_t b2 = (uint32_t)__uint_as_float(v.z), b3 = (uint32_t)__uint_as_float(v.w);
    return __byte_perm(__byte_perm(b0, b1, 0x0040),
                       __byte_perm(b2, b3, 0x0040), 0x5410);
}

// Full adder on bit-planes. 2 LOP3s.
__device__ __forceinline__ void CSA(uint32_t& h, uint32_t& l,
                                    uint32_t a, uint32_t b, uint32_t c) {
    uint32_t u = a ^ b;
    h = (a & b) | (u & c);
    l = u ^ c;
}

// Add 2 packed words into 5-plane accumulators (counts 0..16). ~10 LOP3.
__device__ __forceinline__ void acc2(uint32_t& s0, uint32_t& s1, uint32_t& s2,
                                     uint32_t& s3, uint32_t& s4,
                                     uint32_t p0, uint32_t p1) {
    uint32_t ones = p0 ^ p1, twos = p0 & p1;
    uint32_t c1 = s0 & ones;  s0 ^= ones;              // weight 1
    uint32_t c2; CSA(c2, s1, s1, c1, twos);            // weight 2 (two carries in)
    uint32_t c3 = s2 & c2;    s2 ^= c2;                // weight 4
    uint32_t c4 = s3 & c3;    s3 ^= c3;                // weight 8
    s4 ^= c4;                                          // weight 16
}

__global__ void __launch_bounds__(NTHR, 7) k_fused(
    const uint4* __restrict__ flip4,
    const uint4* __restrict__ weights4,
    const float* __restrict__ vpm,
    float* __restrict__ outf,
    int*  __restrict__ outi,
    int as_float)
{
    __shared__ uint4 sbuf[2][2][NTHR];     // 16KB 2-stage ring, 2 layers/stage
    __shared__ unsigned int red[8];
    __shared__ unsigned int sh;

    const int tid   = threadIdx.x;
    const int warp  = tid >> 5;
    const int lane  = tid & 31;
    const int gt    = blockIdx.x * NTHR + tid;
    const int w     = gt >> 1;                  // packed word (2 threads/word)
    const int half  = gt & 1;                   // 0: layers 0..15, 1: 16..31
    const int lbase = half << 4;

    // Prologue: stages 0 and 1 in flight.
    #pragma unroll
    for (int st = 0; st < 2; st++) {
        cpa16(&sbuf[st][0][tid], &flip4[(size_t)(lbase + st * 2 + 0) * LAYER_U4 + w]);
        cpa16(&sbuf[st][1][tid], &flip4[(size_t)(lbase + st * 2 + 1) * LAYER_U4 + w]);
        CPA_COMMIT();
    }

    // Uniform dtype detect (overlaps prologue): int32 0..255 never sets bits
    // >= 9; float32 encodings of values >= 1.0 do.
    if (tid == 0) {
        const uint32_t* r = (const uint32_t*)flip4;
        uint32_t o = r[0] | r[1] | r[2] | r[3] | r[4] | r[5] | r[6] | r[7];
        sh = (o >> 9) ? 1u : 0u;
    }
    __syncthreads();
    const bool isf = (sh != 0);
    __syncthreads();                            // sh reused later

    // ---- Phase 1: pipelined bit-sliced popcount of 16 layers/thread ----
    uint32_t s0 = 0, s1 = 0, s2 = 0, s3 = 0, s4 = 0;
    if (isf) {
        #pragma unroll
        for (int st = 0; st < NSTAGE; st++) {
            if (st < NSTAGE - 1) CPA_WAIT(1); else CPA_WAIT(0);
            const uint4 va = sbuf[st & 1][0][tid];
            const uint4 vb = sbuf[st & 1][1][tid];
            if (st + 2 < NSTAGE) {
                cpa16(&sbuf[st & 1][0][tid],
                      &flip4[(size_t)(lbase + (st + 2) * 2 + 0) * LAYER_U4 + w]);
                cpa16(&sbuf[st & 1][1][tid],
                      &flip4[(size_t)(lbase + (st + 2) * 2 + 1) * LAYER_U4 + w]);
                CPA_COMMIT();
            }
            acc2(s0, s1, s2, s3, s4, pack4f(va), pack4f(vb));
        }
    } else {
        #pragma unroll
        for (int st = 0; st < NSTAGE; st++) {
            if (st < NSTAGE - 1) CPA_WAIT(1); else CPA_WAIT(0);
            const uint4 va = sbuf[st & 1][0][tid];
            const uint4 vb = sbuf[st & 1][1][tid];
            if (st + 2 < NSTAGE) {
                cpa16(&sbuf[st & 1][0][tid],
                      &flip4[(size_t)(lbase + (st + 2) * 2 + 0) * LAYER_U4 + w]);
                cpa16(&sbuf[st & 1][1][tid],
                      &flip4[(size_t)(lbase + (st + 2) * 2 + 1) * LAYER_U4 + w]);
                CPA_COMMIT();
            }
            acc2(s0, s1, s2, s3, s4, pack4i(va), pack4i(vb));
        }
    }

    // ---- Pair combine: odd lane's 5 planes -> even lane; 6-plane sum ----
    const uint32_t b0 = __shfl_down_sync(0xFFFFFFFFu, s0, 1);
    const uint32_t b1 = __shfl_down_sync(0xFFFFFFFFu, s1, 1);
    const uint32_t b2 = __shfl_down_sync(0xFFFFFFFFu, s2, 1);
    const uint32_t b3 = __shfl_down_sync(0xFFFFFFFFu, s3, 1);
    const uint32_t b4 = __shfl_down_sync(0xFFFFFFFFu, s4, 1);
    uint32_t t[6];
    {
        uint32_t c = s0 & b0;      t[0] = s0 ^ b0;
        uint32_t c2; CSA(c2, t[1], s1, b1, c);
        uint32_t c3; CSA(c3, t[2], s2, b2, c2);
        uint32_t c4; CSA(c4, t[3], s3, b3, c3);
        uint32_t c5; CSA(c5, t[4], s4, b4, c4);
        t[5] = c5;
    }

    // Prefetch weights (even threads only; overlaps the barrier wait)
    uint4 wv = make_uint4(0, 0, 0, 0);
    if (!half) wv = weights4[w];

    // Vote total (even lanes hold valid planes)
    unsigned lanesum = 0;
    if (!half)
        lanesum = __popc(t[0]) + 2 * __popc(t[1]) + 4 * __popc(t[2])
                + 8 * __popc(t[3]) + 16 * __popc(t[4]) + 32 * __popc(t[5]);
    #pragma unroll
    for (int k = 16; k; k >>= 1) lanesum += __shfl_xor_sync(0xFFFFFFFFu, lanesum, k);
    if (lane == 0) red[warp] = lanesum;
    __syncthreads();

    // ---- Grid barrier (replay-safe monotonic counter) ----
    if (tid == 0) {
        unsigned b = 0;
        #pragma unroll
        for (int i = 0; i < 8; i++) b += red[i];
        g_cnt_part[blockIdx.x] = b;
        __threadfence();
        const unsigned old = atomicAdd(&g_arrive, 1u);
        const unsigned target = (old / NBLK) * NBLK + NBLK;
        while (*(volatile unsigned int*)&g_arrive < target) __nanosleep(64);
        __threadfence();
    }
    __syncthreads();

    // ---- Global total -> threshold ----
    {
        unsigned tt = 0;
        for (int i = tid; i < NBLK; i += NTHR) tt += g_cnt_part[i];
        #pragma unroll
        for (int k = 16; k; k >>= 1) tt += __shfl_xor_sync(0xFFFFFFFFu, tt, k);
        if (lane == 0) red[warp] = tt;
        __syncthreads();
        if (tid == 0) {
            unsigned u = 0;
            #pragma unroll
            for (int i = 0; i < 8; i++) u += red[i];
            sh = u;
        }
        __syncthreads();
    }
    const unsigned total = sh;
    // p = max(vote_p_max, mean/32); mask = votes > p*32; integer votes:
    //   votes > th <=> votes > floor(th)
    const float mean = (float)((double)total * (1.0 / (double)TOTAL_BITS));
    const float p    = fmaxf(vpm[0], mean * (1.0f / 32.0f));
    const unsigned tb = (unsigned)floorf(p * 32.0f);

    // ---- Bit-sliced compare count > tb : result IS the packed mask word ----
    uint32_t gtm = 0, eq = 0xFFFFFFFFu;
    #pragma unroll
    for (int k = 5; k >= 0; k--) {
        const uint32_t tk = (uint32_t)(-(int)((tb >> k) & 1u));
        gtm |= eq & t[k] & ~tk;
        eq &= ~(t[k] ^ tk);
    }
    const uint32_t mask = half ? 0u : gtm;

    if (!half) {
        const uint32_t wword = isf ? pack4f(wv) : pack4i(wv);
        const uint32_t xw    = ~(mask ^ wword);    // bytewise XNOR
        if (as_float) {
            float4 o = { (float)( xw        & 0xFFu), (float)((xw >> 8)  & 0xFFu),
                         (float)((xw >> 16) & 0xFFu), (float)((xw >> 24) & 0xFFu) };
            ((float4*)outf)[w] = o;
        } else {
            int4 o = { (int)( xw        & 0xFFu), (int)((xw >> 8)  & 0xFFu),
                       (int)((xw >> 16) & 0xFFu), (int)((xw >> 24) & 0xFFu) };
            ((int4*)outi)[w] = o;
        }
    }

    // ---- Mask popcount partials; last finisher writes the ratio ----
    unsigned mp = __popc(mask);
    #pragma unroll
    for (int k = 16; k; k >>= 1) mp += __shfl_xor_sync(0xFFFFFFFFu, mp, k);
    if (lane == 0) red[warp] = mp;
    __syncthreads();
    if (tid == 0) {
        unsigned b = 0;
        #pragma unroll
        for (int i = 0; i < 8; i++) b += red[i];
        g_mask_part[blockIdx.x] = b;
        __threadfence();
        const unsigned old = atomicAdd(&g_done, 1u);
        sh = ((old % NBLK) == NBLK - 1) ? 1u : 0u;
    }
    __syncthreads();
    if (sh) {
        __threadfence();
        unsigned tt = 0;
        for (int i = tid; i < NBLK; i += NTHR) tt += g_mask_part[i];
        #pragma unroll
        for (int k = 16; k; k >>= 1) tt += __shfl_xor_sync(0xFFFFFFFFu, tt, k);
        if (lane == 0) red[warp] = tt;
        __syncthreads();
        if (tid == 0 && as_float) {
            unsigned u = 0;
            #pragma unroll
            for (int i = 0; i < 8; i++) u += red[i];
            outf[W_ELEMS] = (float)((double)u * (1.0 / (double)TOTAL_BITS));
        }
    }
}

extern "C" void kernel_launch(void* const* d_in, const int* in_sizes, int n_in,
                              void* d_out, int out_size)
{
    // Bind by element count (expansion preserves counts).
    const uint4* weights4 = 0;
    const uint4* flip4    = 0;
    const float* vpm      = 0;
    for (int i = 0; i < n_in; i++) {
        if      (in_sizes[i] == FLIP_ELEMS) flip4    = (const uint4*)d_in[i];
        else if (in_sizes[i] == W_ELEMS)    weights4 = (const uint4*)d_in[i];
        else if (in_sizes[i] == 1)          vpm      = (const float*)d_in[i];
    }
    if (!weights4 || !flip4) {
        weights4 = (const uint4*)d_in[0];
        flip4    = (const uint4*)d_in[1];
        vpm      = (const float*)d_in[n_in - 1];
    }

    const int as_float = (out_size != W_ELEMS) ? 1 : 0;

    k_fused<<<NBLK, NTHR>>>(flip4, weights4, vpm,
                            (float*)d_out, (int*)d_out, as_float);
}

// round 10
// speedup vs baseline: 1.8653x; 1.8653x over previous
#include <cuda_runtime.h>
#include <stdint.h>

// Dataset-fixed shapes. Harness delivers uint8 arrays EXPANDED to one value
// 0..255 per 32-bit element (int32 or float32 — uniform-detected at runtime).
//   weights: 524288 elems, flip: 16777216 elems (32 layers x 524288)
//   out: 524289 f32 = new_weights byte values ++ update_ratio  [or 524288 i32]
#define WORDS       131072            // packed uint32 words
#define LAYERS      32
#define TOTAL_BITS  4194304
#define LAYER_U4    131072            // uint4 per layer (1 uint4 = 1 packed word)
#define FLIP_ELEMS  16777216
#define W_ELEMS     524288
#define NBLK        592               // 4 * 148: every SM gets exactly 4 blocks
#define NTHR        256
#define MAXW        222               // max words per block (ceil(131072/592))
#define NST         8                 // 8 stages x 4 layers
#define RING        3                 // SMEM ring depth

// Monotonic counters (graph-replay-safe: each run adds exactly NBLK; target is
// the next multiple of NBLK). Zero-initialized at module load.
__device__ unsigned int g_arrive = 0;
__device__ unsigned int g_done   = 0;
__device__ unsigned int g_cnt_part[NBLK];
__device__ unsigned int g_mask_part[NBLK];

// ---- TMA bulk + mbarrier helpers ----
__device__ __forceinline__ uint32_t s2u(const void* p) {
    return (uint32_t)__cvta_generic_to_shared(p);
}
__device__ __forceinline__ void mbar_init(uint32_t a, uint32_t cnt) {
    asm volatile("mbarrier.init.shared.b64 [%0], %1;" :: "r"(a), "r"(cnt) : "memory");
}
__device__ __forceinline__ void mbar_expect_tx(uint32_t a, uint32_t bytes) {
    asm volatile("mbarrier.arrive.expect_tx.shared.b64 _, [%0], %1;"
                 :: "r"(a), "r"(bytes) : "memory");
}
__device__ __forceinline__ void bulk_g2s(uint32_t sdst, const void* gsrc,
                                         uint32_t bytes, uint32_t mbar) {
    asm volatile("cp.async.bulk.shared::cta.global.mbarrier::complete_tx::bytes "
                 "[%0], [%1], %2, [%3];"
                 :: "r"(sdst), "l"(gsrc), "r"(bytes), "r"(mbar) : "memory");
}
__device__ __forceinline__ void mbar_wait(uint32_t a, uint32_t parity) {
    asm volatile(
        "{\n\t.reg .pred P;\n"
        "W%=:\n\t"
        "mbarrier.try_wait.parity.acquire.cta.shared::cta.b64 P, [%0], %1, 0x989680;\n\t"
        "@P bra D%=;\n\t"
        "bra W%=;\n"
        "D%=:\n\t}"
        :: "r"(a), "r"(parity) : "memory");
}

// 4 expanded elements -> one packed byte word (elem k -> byte k)
__device__ __forceinline__ uint32_t pack4i(uint4 v) {   // int32-expanded path
    return __byte_perm(__byte_perm(v.x, v.y, 0x0040),
                       __byte_perm(v.z, v.w, 0x0040), 0x5410);
}
__device__ __forceinline__ uint32_t pack4f(uint4 v) {   // float32-expanded path
    uint32_t b0 = (uint32_t)__uint_as_float(v.x), b1 = (uint32_t)__uint_as_float(v.y);
    uint32_t b2 = (uint32_t)__uint_as_float(v.z), b3 = (uint32_t)__uint_as_float(v.w);
    return __byte_perm(__byte_perm(b0, b1, 0x0040),
                       __byte_perm(b2, b3, 0x0040), 0x5410);
}

// Full adder on bit-planes. 2 LOP3s.
__device__ __forceinline__ void CSA(uint32_t& h, uint32_t& l,
                                    uint32_t a, uint32_t b, uint32_t c) {
    uint32_t u = a ^ b;
    h = (a & b) | (u & c);
    l = u ^ c;
}

// Add 4 packed words into bit-plane accumulators s[0..5]. ~14 LOP3.
__device__ __forceinline__ void acc4(uint32_t* s, uint32_t p0, uint32_t p1,
                                     uint32_t p2, uint32_t p3) {
    uint32_t c1, x1;
    CSA(c1, x1, p0, p1, p2);
    uint32_t ones = x1 ^ p3, c2 = x1 & p3;
    uint32_t twos = c1 ^ c2, fours = c1 & c2;
    uint32_t k1 = s[0] & ones;  s[0] ^= ones;                 // weight 1
    uint32_t k2; CSA(k2, s[1], s[1], k1, twos);               // weight 2
    uint32_t k3; CSA(k3, s[2], s[2], k2, fours);              // weight 4
    uint32_t k4 = s[3] & k3;    s[3] ^= k3;                   // weight 8
    uint32_t k5 = s[4] & k4;    s[4] ^= k4;                   // weight 16
    s[5] ^= k5;                                               // weight 32
}

__global__ void __launch_bounds__(NTHR, 4) k_fused(
    const uint4* __restrict__ flip4,
    const uint4* __restrict__ weights4,
    const float* __restrict__ vpm,
    float* __restrict__ outf,
    int*  __restrict__ outi,
    int as_float)
{
    __shared__ uint4 sbuf[RING][4][MAXW];      // ~42.6KB ring, 4 layers/stage
    __shared__ unsigned long long mbar_s[RING];
    __shared__ unsigned int red[8];
    __shared__ unsigned int sh;

    const int tid  = threadIdx.x;
    const int warp = tid >> 5;
    const int lane = tid & 31;

    // Balanced ragged tile: 221 or 222 words per block.
    const int wbeg = (int)(((unsigned long long)blockIdx.x       * WORDS) / NBLK);
    const int wend = (int)(((unsigned long long)(blockIdx.x + 1) * WORDS) / NBLK);
    const int nw   = wend - wbeg;
    const bool has = tid < nw;
    const int  w   = wbeg + (has ? tid : 0);
    const uint32_t layer_bytes = (uint32_t)nw * 16u;          // mult of 16
    const uint32_t stage_bytes = layer_bytes * 4u;

    uint32_t mb[RING];
    #pragma unroll
    for (int r = 0; r < RING; r++) mb[r] = s2u(&mbar_s[r]);

    if (tid == 0) {
        #pragma unroll
        for (int r = 0; r < RING; r++) mbar_init(mb[r], 1);
        // Uniform dtype detect: int32 0..255 never sets bits >= 9; float32
        // encodings of values >= 1.0 do.
        const uint32_t* r8 = (const uint32_t*)flip4;
        uint32_t o = r8[0] | r8[1] | r8[2] | r8[3] | r8[4] | r8[5] | r8[6] | r8[7];
        sh = (o >> 9) ? 1u : 0u;
    }
    __syncthreads();
    const bool isf = (sh != 0);

    // Prologue: issue stages 0..2 (TMA producer, single thread).
    if (tid == 0) {
        #pragma unroll
        for (int st = 0; st < RING; st++) {
            mbar_expect_tx(mb[st], stage_bytes);
            #pragma unroll
            for (int j = 0; j < 4; j++)
                bulk_g2s(s2u(&sbuf[st][j][0]),
                         &flip4[(size_t)(st * 4 + j) * LAYER_U4 + wbeg],
                         layer_bytes, mb[st]);
        }
    }
    __syncthreads();   // sh consumed; mbar inits visible before waits

    // ---- Phase 1: TMA-fed bit-sliced popcount of 32 layers ----
    uint32_t s[6] = {0, 0, 0, 0, 0, 0};
    #pragma unroll
    for (int st = 0; st < NST; st++) {
        const int slot = st % RING;
        const uint32_t par = (uint32_t)((st / RING) & 1);
        mbar_wait(mb[slot], par);
        if (has) {
            const uint4 v0 = sbuf[slot][0][tid];
            const uint4 v1 = sbuf[slot][1][tid];
            const uint4 v2 = sbuf[slot][2][tid];
            const uint4 v3 = sbuf[slot][3][tid];
            if (isf) acc4(s, pack4f(v0), pack4f(v1), pack4f(v2), pack4f(v3));
            else     acc4(s, pack4i(v0), pack4i(v1), pack4i(v2), pack4i(v3));
        }
        __syncthreads();                       // all reads done -> slot free
        if (st + RING < NST && tid == 0) {     // refill slot with stage st+RING
            const int ns = st + RING;
            mbar_expect_tx(mb[slot], stage_bytes);
            #pragma unroll
            for (int j = 0; j < 4; j++)
                bulk_g2s(s2u(&sbuf[slot][j][0]),
                         &flip4[(size_t)(ns * 4 + j) * LAYER_U4 + wbeg],
                         layer_bytes, mb[slot]);
        }
    }

    // Prefetch weights (overlaps the barrier wait)
    uint4 wv = make_uint4(0, 0, 0, 0);
    if (has) wv = weights4[w];

    // This thread's vote total: sum_k 2^k * popc(s_k)  (idle threads: 0)
    unsigned lanesum = __popc(s[0]) + 2 * __popc(s[1]) + 4 * __popc(s[2])
                     + 8 * __popc(s[3]) + 16 * __popc(s[4]) + 32 * __popc(s[5]);
    #pragma unroll
    for (int k = 16; k; k >>= 1) lanesum += __shfl_xor_sync(0xFFFFFFFFu, lanesum, k);
    if (lane == 0) red[warp] = lanesum;
    __syncthreads();

    // ---- Grid barrier (replay-safe monotonic counter) ----
    if (tid == 0) {
        unsigned b = 0;
        #pragma unroll
        for (int i = 0; i < 8; i++) b += red[i];
        g_cnt_part[blockIdx.x] = b;
        __threadfence();
        const unsigned old = atomicAdd(&g_arrive, 1u);
        const unsigned target = (old / NBLK) * NBLK + NBLK;
        while (*(volatile unsigned int*)&g_arrive < target) __nanosleep(64);
        __threadfence();
    }
    __syncthreads();

    // ---- Global total -> threshold ----
    {
        unsigned t = 0;
        for (int i = tid; i < NBLK; i += NTHR) t += g_cnt_part[i];
        #pragma unroll
        for (int k = 16; k; k >>= 1) t += __shfl_xor_sync(0xFFFFFFFFu, t, k);
        if (lane == 0) red[warp] = t;
        __syncthreads();
        if (tid == 0) {
            unsigned tt = 0;
            #pragma unroll
            for (int i = 0; i < 8; i++) tt += red[i];
            sh = tt;
        }
        __syncthreads();
    }
    const unsigned total = sh;
    // p = max(vote_p_max, mean/32); mask = votes > p*32; integer votes:
    //   votes > th <=> votes > floor(th)
    const float mean = (float)((double)total * (1.0 / (double)TOTAL_BITS));
    const float p    = fmaxf(vpm[0], mean * (1.0f / 32.0f));
    const unsigned tb = (unsigned)floorf(p * 32.0f);

    // ---- Bit-sliced compare count > tb : result IS the packed mask word ----
    uint32_t gt = 0, eq = 0xFFFFFFFFu;
    #pragma unroll
    for (int k = 5; k >= 0; k--) {
        const uint32_t tk = (uint32_t)(-(int)((tb >> k) & 1u));
        gt |= eq & s[k] & ~tk;
        eq &= ~(s[k] ^ tk);
    }
    const uint32_t mask = has ? gt : 0u;

    if (has) {
        const uint32_t wword = isf ? pack4f(wv) : pack4i(wv);
        const uint32_t xw    = ~(mask ^ wword);     // bytewise XNOR
        if (as_float) {
            float4 o = { (float)( xw        & 0xFFu), (float)((xw >> 8)  & 0xFFu),
                         (float)((xw >> 16) & 0xFFu), (float)((xw >> 24) & 0xFFu) };
            ((float4*)outf)[w] = o;
        } else {
            int4 o = { (int)( xw        & 0xFFu), (int)((xw >> 8)  & 0xFFu),
                       (int)((xw >> 16) & 0xFFu), (int)((xw >> 24) & 0xFFu) };
            ((int4*)outi)[w] = o;
        }
    }

    // ---- Mask popcount partials; last finisher writes the ratio ----
    unsigned mp = __popc(mask);
    #pragma unroll
    for (int k = 16; k; k >>= 1) mp += __shfl_xor_sync(0xFFFFFFFFu, mp, k);
    if (lane == 0) red[warp] = mp;
    __syncthreads();
    if (tid == 0) {
        unsigned b = 0;
        #pragma unroll
        for (int i = 0; i < 8; i++) b += red[i];
        g_mask_part[blockIdx.x] = b;
        __threadfence();
        const unsigned old = atomicAdd(&g_done, 1u);
        sh = ((old % NBLK) == NBLK - 1) ? 1u : 0u;
    }
    __syncthreads();
    if (sh) {
        __threadfence();
        unsigned t = 0;
        for (int i = tid; i < NBLK; i += NTHR) t += g_mask_part[i];
        #pragma unroll
        for (int k = 16; k; k >>= 1) t += __shfl_xor_sync(0xFFFFFFFFu, t, k);
        if (lane == 0) red[warp] = t;
        __syncthreads();
        if (tid == 0 && as_float) {
            unsigned tt = 0;
            #pragma unroll
            for (int i = 0; i < 8; i++) tt += red[i];
            outf[W_ELEMS] = (float)((double)tt * (1.0 / (double)TOTAL_BITS));
        }
    }
}

extern "C" void kernel_launch(void* const* d_in, const int* in_sizes, int n_in,
                              void* d_out, int out_size)
{
    // Bind by element count (expansion preserves counts).
    const uint4* weights4 = 0;
    const uint4* flip4    = 0;
    const float* vpm      = 0;
    for (int i = 0; i < n_in; i++) {
        if      (in_sizes[i] == FLIP_ELEMS) flip4    = (const uint4*)d_in[i];
        else if (in_sizes[i] == W_ELEMS)    weights4 = (const uint4*)d_in[i];
        else if (in_sizes[i] == 1)          vpm      = (const float*)d_in[i];
    }
    if (!weights4 || !flip4) {
        weights4 = (const uint4*)d_in[0];
        flip4    = (const uint4*)d_in[1];
        vpm      = (const float*)d_in[n_in - 1];
    }

    const int as_float = (out_size != W_ELEMS) ? 1 : 0;

    k_fused<<<NBLK, NTHR>>>(flip4, weights4, vpm,
                            (float*)d_out, (int*)d_out, as_float);
}